// round 7
// baseline (speedup 1.0000x reference)
#include <cuda_runtime.h>
#include <cstdint>

#define NB    2
#define NPTS  16384
#define MC3   8192
#define NROI  128
#define NKP   2048
#define CBEV  256
#define CRAW  32
#define CC3   64
#define CF    (CBEV + CRAW + CC3)   // 352
#define COUT  128
#define HW    188
#define GRIDC 24
#define NCELL (GRIDC * GRIDC)       // 576
#define NCHK  512                   // 32-point chunks
#define FULLM 0xffffffffu

typedef unsigned long long ull;

// monotonic float <-> uint key (total order; umax on key == fmax)
__device__ __forceinline__ unsigned fkey(float f) {
    unsigned b = __float_as_uint(f);
    return b ^ ((unsigned)((int)b >> 31) | 0x80000000u);
}
__device__ __forceinline__ float keyf(unsigned k) {
    unsigned b = (k & 0x80000000u) ? (k ^ 0x80000000u) : ~k;
    return __uint_as_float(b);
}

// ---------------- scratch (device globals; no allocation allowed) -----------
__device__ float g_px[NB][NPTS], g_py[NB][NPTS], g_pz[NB][NPTS];
__device__ unsigned char g_valid[NB][NPTS];
__device__ unsigned short g_cell[NB][NPTS];
__device__ int g_cellstart[NB][NCELL], g_cellcur[NB][NCELL];
__device__ int g_nvalid[NB];
__device__ float g_sx[NB][NPTS], g_sy[NB][NPTS], g_sz[NB][NPTS];   // sorted order
__device__ unsigned short g_perm[NB][NPTS];
__device__ float4 g_meta[NB][NCHK];
__device__ float g_cx[NB][MC3], g_cy[NB][MC3], g_cz[NB][MC3];
__device__ float g_kpx[NB][NKP], g_kpy[NB][NKP], g_kpz[NB][NKP];
__device__ float g_fraw[NB * NPTS * CRAW];
__device__ float g_fc3[NB * MC3 * CC3];
__device__ float g_feats[NB * NKP * CF];

// ---------------- 1) SoA copy + ROI validity + cell id ----------------------
__global__ void prep_points_kernel(const float* __restrict__ points,
                                   const float* __restrict__ bboxes) {
    int tid = blockIdx.x * blockDim.x + threadIdx.x;
    if (tid >= NB * NPTS) return;
    int b = tid / NPTS, i = tid % NPTS;
    const float* p = points + (size_t)tid * 5;
    float x = p[0], y = p[1], z = p[2];
    g_px[b][i] = x; g_py[b][i] = y; g_pz[b][i] = z;

    float best = 3.0e38f;
    int bidx = 0;
    const float* bb0 = bboxes + (size_t)b * NROI * 7;
    for (int r = 0; r < NROI; ++r) {
        const float* bb = bb0 + r * 7;
        float dx = x - bb[0], dy = y - bb[1], dz = z - bb[2];
        float d = __fsqrt_rn(dx * dx + dy * dy + dz * dz);
        if (d < best) { best = d; bidx = r; }
    }
    const float* bb = bb0 + bidx * 7;
    float hx = bb[3] * 0.5f, hy = bb[4] * 0.5f, hz = bb[5] * 0.5f;
    float rm = __fsqrt_rn(hx * hx + hy * hy + hz * hz);
    g_valid[b][i] = (best < rm + 2.4f) ? 1 : 0;

    const float inv = (float)GRIDC / 150.4f;
    int cx = min(GRIDC - 1, max(0, (int)((x + 75.2f) * inv)));
    int cy = min(GRIDC - 1, max(0, (int)((y + 75.2f) * inv)));
    g_cell[b][i] = (unsigned short)(cy * GRIDC + cx);
}

__global__ void prep_c3_kernel(const float* __restrict__ conv3) {
    int tid = blockIdx.x * blockDim.x + threadIdx.x;
    if (tid >= NB * MC3) return;
    int b = tid / MC3, i = tid % MC3;
    const float* p = conv3 + (size_t)tid * 67;
    g_cx[b][i] = p[0]; g_cy[b][i] = p[1]; g_cz[b][i] = p[2];
}

// ---------------- 2) cell histogram + scan (one block per batch) ------------
__global__ void histscan_kernel() {
    __shared__ int h[NCELL];
    __shared__ int sa[NCELL], sb[NCELL];
    int b = blockIdx.x, t = threadIdx.x;   // 576 threads
    h[t] = 0;
    __syncthreads();
    for (int i = t; i < NPTS; i += NCELL)
        if (g_valid[b][i]) atomicAdd(&h[g_cell[b][i]], 1);
    __syncthreads();
    sa[t] = h[t];
    __syncthreads();
    int* src = sa; int* dst = sb;
    for (int off = 1; off < NCELL; off <<= 1) {
        int v = src[t];
        if (t >= off) v += src[t - off];
        dst[t] = v;
        __syncthreads();
        int* tmp = src; src = dst; dst = tmp;
    }
    int incl = src[t];
    int start = incl - h[t];
    g_cellstart[b][t] = start;
    g_cellcur[b][t] = start;
    if (t == NCELL - 1) g_nvalid[b] = incl;
}

// ---------------- 3) scatter valid points into sorted order -----------------
__global__ void scatter_kernel() {
    int tid = blockIdx.x * blockDim.x + threadIdx.x;
    if (tid >= NB * NPTS) return;
    int b = tid / NPTS, i = tid % NPTS;
    if (!g_valid[b][i]) return;
    int cell = g_cell[b][i];
    int pos = atomicAdd(&g_cellcur[b][cell], 1);
    g_sx[b][pos] = g_px[b][i];
    g_sy[b][pos] = g_py[b][i];
    g_sz[b][pos] = g_pz[b][i];
    g_perm[b][pos] = (unsigned short)i;
}

// ---------------- 4) per-chunk bounding spheres (warp per chunk) ------------
__global__ void bounds_kernel() {
    int b = blockIdx.y;
    int w = threadIdx.x >> 5, j = threadIdx.x & 31;
    int c = blockIdx.x * 8 + w;          // 64 blocks * 8 warps = 512 chunks
    int n = g_nvalid[b];
    int sz = min(32, n - 32 * c);
    float4 out;
    if (sz <= 0) {
        out = make_float4(1.0e8f, 1.0e8f, 1.0e8f, 0.0f);
    } else {
        bool in = (j < sz);
        int pos = 32 * c + j;
        float x = in ? g_sx[b][pos] : 0.0f;
        float y = in ? g_sy[b][pos] : 0.0f;
        float z = in ? g_sz[b][pos] : 0.0f;
        float xn = keyf(__reduce_min_sync(FULLM, fkey(in ? x : 3.0e38f)));
        float xm = keyf(__reduce_max_sync(FULLM, fkey(in ? x : -3.0e38f)));
        float yn = keyf(__reduce_min_sync(FULLM, fkey(in ? y : 3.0e38f)));
        float ym = keyf(__reduce_max_sync(FULLM, fkey(in ? y : -3.0e38f)));
        float zn = keyf(__reduce_min_sync(FULLM, fkey(in ? z : 3.0e38f)));
        float zm = keyf(__reduce_max_sync(FULLM, fkey(in ? z : -3.0e38f)));
        float ccx = (xn + xm) * 0.5f, ccy = (yn + ym) * 0.5f, ccz = (zn + zm) * 0.5f;
        float dx = x - ccx, dy = y - ccy, dz = z - ccz;
        float d2 = in ? (dx * dx + dy * dy + dz * dz) : -1.0f;
        float r = __fsqrt_rn(keyf(__reduce_max_sync(FULLM, fkey(d2))));
        out = make_float4(ccx, ccy, ccz, r * 1.00002f + 1.0e-3f);
    }
    if (j == 0) g_meta[b][c] = out;
}

// ---------------- 5) per-point MLPs -----------------------------------------
__global__ void fraw_kernel(const float* __restrict__ points,
                            const float* __restrict__ W,
                            const float* __restrict__ bias) {
    int tid = blockIdx.x * blockDim.x + threadIdx.x;
    if (tid >= NB * NPTS * CRAW) return;
    int c = tid & (CRAW - 1);
    int pi = tid >> 5;
    const float* p = points + (size_t)pi * 5;
    float v = p[3] * W[c] + p[4] * W[CRAW + c] + bias[c];
    g_fraw[tid] = fmaxf(v, 0.0f);
}

__global__ void fc3_kernel(const float* __restrict__ conv3,
                           const float* __restrict__ W,
                           const float* __restrict__ bias) {
    int tid = blockIdx.x * blockDim.x + threadIdx.x;
    if (tid >= NB * MC3 * CC3) return;
    int c = tid & (CC3 - 1);
    int pi = tid >> 6;
    const float* p = conv3 + (size_t)pi * 67 + 3;
    float acc = 0.0f;
    #pragma unroll 8
    for (int k = 0; k < CC3; ++k) acc += p[k] * W[k * CC3 + c];
    g_fc3[tid] = fmaxf(acc + bias[c], 0.0f);
}

// ---------------- 6) warp-per-chunkset exact FPS ----------------------------
// Warp w owns chunks 32w..32w+31; lane j owns point j of each chunk
// (pos = 32*(32w+c)+j, natural sorted order, conflict-free LDS).
// dd[32] statically indexed registers. Lane c holds chunk (32w+c)'s bounding
// sphere (mt) and current max (kmaxv) -> data-parallel prune + 1 ballot.
// Update loop statically unrolled, guarded by warp-uniform act bits; REDUX
// only for active chunks (pipelined). Selection gated on BLOCK max (rare).
__global__ void __launch_bounds__(512, 1) fps_kernel() {
    extern __shared__ float smem[];
    float* s_x = smem;            // [16384] sorted
    float* s_y = smem + NPTS;
    float* s_z = smem + 2 * NPTS;
    __shared__ unsigned s_wmax[16];
    __shared__ int s_sel[2];
    __shared__ float s_kx, s_ky, s_kz;

    int b = blockIdx.x, t = threadIdx.x;
    int w = t >> 5, j = t & 31;
    int n = g_nvalid[b];

    for (int i = t; i < NPTS; i += 512) {
        s_x[i] = g_sx[b][i];
        s_y[i] = g_sy[b][i];
        s_z[i] = g_sz[b][i];
    }
    // orig indices of point j of chunks 32w+c, packed 2 per register
    unsigned pr[16];
    #pragma unroll
    for (int q = 0; q < 16; ++q) {
        unsigned lo16 = g_perm[b][1024 * w + 32 * (2 * q) + j];
        unsigned hi16 = g_perm[b][1024 * w + 32 * (2 * q + 1) + j];
        pr[q] = lo16 | (hi16 << 16);
    }
    float4 mt = g_meta[b][32 * w + j];    // lane j: chunk 32w+j's sphere
    float kmaxv = (32 * (32 * w + j) < n) ? 1.0e10f : -1.0e10f;  // chunk max
    if (t == 0) { s_sel[0] = 0x7fffffff; s_sel[1] = 0x7fffffff; }

    float dd[32];
    float thrmax = -3.0e38f;
    #pragma unroll
    for (int c = 0; c < 32; ++c) {
        int pos = 1024 * w + 32 * c + j;
        float v = (pos < n) ? 1.0e10f : -1.0e10f;
        dd[c] = v;
        thrmax = fmaxf(thrmax, v);
    }
    __syncthreads();

    for (int it = 0; it < NKP; ++it) {
        // ---- A: block max (thread max -> warp REDUX -> 16-wide REDUX) ----
        unsigned wk = __reduce_max_sync(FULLM, fkey(thrmax));
        if (j == 0) s_wmax[w] = wk;
        if (t == 0) s_sel[(it + 1) & 1] = 0x7fffffff;
        __syncthreads();                                   // bar1
        unsigned k2 = __reduce_max_sync(FULLM, s_wmax[j & 15]);
        float V = keyf(k2);

        // ---- B: rare candidate rescan (gated on BLOCK max) ----
        int candv = 0x7fffffff, cpos = 0;
        if (thrmax == V) {
            #pragma unroll
            for (int c = 0; c < 32; ++c) {
                if (dd[c] == V) {
                    unsigned o = (pr[c >> 1] >> (16 * (c & 1))) & 0xffffu;
                    if ((int)o < candv) { candv = (int)o; cpos = 1024 * w + 32 * c + j; }
                }
            }
            atomicMin(&s_sel[it & 1], candv);
        }
        __syncthreads();                                   // bar2

        // ---- C: unique winner publishes keypoint ----
        int sel = s_sel[it & 1];
        if (candv == sel) {
            float x = s_x[cpos], y = s_y[cpos], z = s_z[cpos];
            s_kx = x; s_ky = y; s_kz = z;
            g_kpx[b][it] = x; g_kpy[b][it] = y; g_kpz[b][it] = z;
        }
        __syncthreads();                                   // bar3
        if (it == NKP - 1) break;
        float kx = s_kx, ky = s_ky, kz = s_kz;

        // ---- D: data-parallel prune (lane c judges chunk 32w+c) ----
        float dxc = kx - mt.x, dyc = ky - mt.y, dzc = kz - mt.z;
        float dc = __fsqrt_rn(dxc * dxc + dyc * dyc + dzc * dzc);
        float lhs = dc - mt.w - 1.0e-3f;
        bool active = !((lhs > 0.0f) && (lhs * lhs * 0.99999f > kmaxv));
        unsigned act = __ballot_sync(FULLM, active);
        if (act) {
            #pragma unroll
            for (int c = 0; c < 32; ++c) {
                if (act & (1u << c)) {                     // warp-uniform branch
                    int pos = 1024 * w + 32 * c + j;
                    float dx = s_x[pos] - kx;
                    float dy = s_y[pos] - ky;
                    float dz = s_z[pos] - kz;
                    float nd = fmaf(dz, dz, fmaf(dy, dy, dx * dx));
                    float v = fminf(dd[c], nd);
                    dd[c] = v;
                    unsigned nm = __reduce_max_sync(FULLM, fkey(v));
                    if (j == c) kmaxv = keyf(nm);
                }
            }
            float vm = dd[0];
            #pragma unroll
            for (int c = 1; c < 32; ++c) vm = fmaxf(vm, dd[c]);
            thrmax = vm;
        }
    }
}

// ---------------- 7) bilinear BEV sampling ----------------------------------
__global__ void bev_kernel(const float* __restrict__ sf) {
    int k = blockIdx.x, b = blockIdx.y, c = threadIdx.x;
    float kx = g_kpx[b][k], ky = g_kpy[b][k];
    float xi = __fdiv_rn(__fdiv_rn(kx - (-75.2f), 0.1f), 8.0f);
    float yi = __fdiv_rn(__fdiv_rn(ky - (-75.2f), 0.1f), 8.0f);
    int x0 = min(max((int)floorf(xi), 0), HW - 1);
    int x1 = min(x0 + 1, HW - 1);
    int y0 = min(max((int)floorf(yi), 0), HW - 1);
    int y1 = min(y0 + 1, HW - 1);
    float xf0 = (float)x0, xf1 = (float)x1, yf0 = (float)y0, yf1 = (float)y1;
    float wa = (xf1 - xi) * (yf1 - yi);
    float wb = (xf1 - xi) * (yi - yf0);
    float wc = (xi - xf0) * (yf1 - yi);
    float wd = (xi - xf0) * (yi - yf0);
    const float* im = sf + ((size_t)b * CBEV + c) * (HW * HW);
    float Ia = im[y0 * HW + x0];
    float Ib = im[y1 * HW + x0];
    float Ic = im[y0 * HW + x1];
    float Id = im[y1 * HW + x1];
    g_feats[((size_t)b * NKP + k) * CF + c] = Ia * wa + Ib * wb + Ic * wc + Id * wd;
}

// ---------------- 8) radius aggregation (ballot-broadcast) ------------------
__global__ void agg_raw_kernel(float r2) {
    int b = blockIdx.y;
    int warp = threadIdx.x >> 5, lane = threadIdx.x & 31;
    int k = blockIdx.x * 8 + warp;
    float kx = g_kpx[b][k], ky = g_kpy[b][k], kz = g_kpz[b][k];
    float acc = 0.0f;
    int cnt = 0;
    __shared__ float sx[256], sy[256], sz[256];
    for (int base = 0; base < NPTS; base += 256) {
        __syncthreads();
        int i = base + threadIdx.x;
        sx[threadIdx.x] = g_px[b][i];
        sy[threadIdx.x] = g_py[b][i];
        sz[threadIdx.x] = g_pz[b][i];
        __syncthreads();
        #pragma unroll
        for (int s = 0; s < 8; ++s) {
            int jj = s * 32 + lane;
            float dx = sx[jj] - kx, dy = sy[jj] - ky, dz = sz[jj] - kz;
            float d2 = dx * dx + dy * dy + dz * dz;
            unsigned m = __ballot_sync(FULLM, d2 < r2);
            while (m) {
                int src = __ffs(m) - 1;
                m &= m - 1;
                int gp = base + s * 32 + src;
                acc += g_fraw[((size_t)b * NPTS + gp) * CRAW + lane];
                cnt++;
            }
        }
    }
    float c = fmaxf((float)cnt, 1.0f);
    g_feats[((size_t)b * NKP + k) * CF + CBEV + lane] = acc / c;
}

__global__ void agg_c3_kernel(float r2) {
    int b = blockIdx.y;
    int warp = threadIdx.x >> 5, lane = threadIdx.x & 31;
    int k = blockIdx.x * 8 + warp;
    float kx = g_kpx[b][k], ky = g_kpy[b][k], kz = g_kpz[b][k];
    float acc0 = 0.0f, acc1 = 0.0f;
    int cnt = 0;
    __shared__ float sx[256], sy[256], sz[256];
    for (int base = 0; base < MC3; base += 256) {
        __syncthreads();
        int i = base + threadIdx.x;
        sx[threadIdx.x] = g_cx[b][i];
        sy[threadIdx.x] = g_cy[b][i];
        sz[threadIdx.x] = g_cz[b][i];
        __syncthreads();
        #pragma unroll
        for (int s = 0; s < 8; ++s) {
            int jj = s * 32 + lane;
            float dx = sx[jj] - kx, dy = sy[jj] - ky, dz = sz[jj] - kz;
            float d2 = dx * dx + dy * dy + dz * dz;
            unsigned m = __ballot_sync(FULLM, d2 < r2);
            while (m) {
                int src = __ffs(m) - 1;
                m &= m - 1;
                int gp = base + s * 32 + src;
                const float* fp = g_fc3 + ((size_t)b * MC3 + gp) * CC3;
                acc0 += fp[lane];
                acc1 += fp[lane + 32];
                cnt++;
            }
        }
    }
    float c = fmaxf((float)cnt, 1.0f);
    float* o = g_feats + ((size_t)b * NKP + k) * CF + CBEV + CRAW;
    o[lane] = acc0 / c;
    o[lane + 32] = acc1 / c;
}

// ---------------- 9) fuse GEMM + BN + ReLU ----------------------------------
#define ROWS_PB 16
__global__ void fuse_kernel(const float* __restrict__ W,
                            const float* __restrict__ gamma,
                            const float* __restrict__ beta,
                            const float* __restrict__ mean,
                            const float* __restrict__ var,
                            float* __restrict__ out) {
    __shared__ float sf[ROWS_PB][CF];
    int row0 = blockIdx.x * ROWS_PB;
    int tid = threadIdx.x;
    for (int idx = tid; idx < ROWS_PB * CF; idx += 128) {
        ((float*)sf)[idx] = g_feats[(size_t)row0 * CF + idx];
    }
    __syncthreads();
    int c = tid;
    float acc[ROWS_PB];
    #pragma unroll
    for (int r = 0; r < ROWS_PB; ++r) acc[r] = 0.0f;
    for (int k = 0; k < CF; ++k) {
        float wv = W[k * COUT + c];
        #pragma unroll
        for (int r = 0; r < ROWS_PB; ++r) acc[r] += sf[r][k] * wv;
    }
    float mu = mean[c];
    float iv = rsqrtf(var[c] + 1e-5f);
    float g = gamma[c], be = beta[c];
    #pragma unroll
    for (int r = 0; r < ROWS_PB; ++r) {
        float v = (acc[r] - mu) * iv * g + be;
        out[(size_t)(row0 + r) * COUT + c] = fmaxf(v, 0.0f);
    }
}

// ---------------- 10) keypoints output --------------------------------------
__global__ void kpout_kernel(float* __restrict__ out) {
    int tid = blockIdx.x * blockDim.x + threadIdx.x;
    if (tid >= NB * NKP * 3) return;
    int b = tid / (NKP * 3);
    int rem = tid % (NKP * 3);
    int k = rem / 3, d = rem % 3;
    float v = (d == 0) ? g_kpx[b][k] : (d == 1 ? g_kpy[b][k] : g_kpz[b][k]);
    out[(size_t)NB * NKP * COUT + tid] = v;
}

// ---------------- launcher ---------------------------------------------------
extern "C" void kernel_launch(void* const* d_in, const int* in_sizes, int n_in,
                              void* d_out, int out_size) {
    const float* points  = (const float*)d_in[0];
    const float* bboxes  = (const float*)d_in[1];
    const float* spatial = (const float*)d_in[2];
    const float* conv3   = (const float*)d_in[3];
    const float* W_raw   = (const float*)d_in[4];
    const float* b_raw   = (const float*)d_in[5];
    const float* W_c3    = (const float*)d_in[6];
    const float* b_c3    = (const float*)d_in[7];
    const float* W_fuse  = (const float*)d_in[8];
    const float* bn_g    = (const float*)d_in[9];
    const float* bn_b    = (const float*)d_in[10];
    const float* bn_m    = (const float*)d_in[11];
    const float* bn_v    = (const float*)d_in[12];
    float* out = (float*)d_out;

    const int fps_smem = 3 * NPTS * (int)sizeof(float);   // 196608 B
    cudaFuncSetAttribute(fps_kernel, cudaFuncAttributeMaxDynamicSharedMemorySize,
                         fps_smem);

    prep_points_kernel<<<(NB * NPTS + 255) / 256, 256>>>(points, bboxes);
    prep_c3_kernel<<<(NB * MC3 + 255) / 256, 256>>>(conv3);
    histscan_kernel<<<NB, NCELL>>>();
    scatter_kernel<<<(NB * NPTS + 255) / 256, 256>>>();
    bounds_kernel<<<dim3(64, NB), 256>>>();
    fraw_kernel<<<(NB * NPTS * CRAW + 255) / 256, 256>>>(points, W_raw, b_raw);
    fc3_kernel<<<(NB * MC3 * CC3 + 255) / 256, 256>>>(conv3, W_c3, b_c3);
    fps_kernel<<<NB, 512, fps_smem>>>();
    bev_kernel<<<dim3(NKP, NB), CBEV>>>(spatial);
    agg_raw_kernel<<<dim3(NKP / 8, NB), 256>>>(0.8f * 0.8f);
    agg_c3_kernel<<<dim3(NKP / 8, NB), 256>>>(1.6f * 1.6f);
    fuse_kernel<<<(NB * NKP) / ROWS_PB, COUT>>>(W_fuse, bn_g, bn_b, bn_m, bn_v, out);
    kpout_kernel<<<(NB * NKP * 3 + 255) / 256, 256>>>(out);
}

// round 8
// speedup vs baseline: 1.7094x; 1.7094x over previous
#include <cuda_runtime.h>
#include <cstdint>

#define NB    2
#define NPTS  16384
#define MC3   8192
#define NROI  128
#define NKP   2048
#define CBEV  256
#define CRAW  32
#define CC3   64
#define CF    (CBEV + CRAW + CC3)   // 352
#define COUT  128
#define HW    188
#define GRIDC 24
#define NCELL (GRIDC * GRIDC)       // 576
#define NCHK  512                   // 32-point chunks
#define FULLM 0xffffffffu

typedef unsigned long long ull;

// monotonic float <-> uint key (total order; umax on key == fmax)
__device__ __forceinline__ unsigned fkey(float f) {
    unsigned b = __float_as_uint(f);
    return b ^ ((unsigned)((int)b >> 31) | 0x80000000u);
}

// ---------------- scratch (device globals; no allocation allowed) -----------
__device__ float g_px[NB][NPTS], g_py[NB][NPTS], g_pz[NB][NPTS];
__device__ unsigned char g_valid[NB][NPTS];
__device__ unsigned short g_cell[NB][NPTS];
__device__ int g_cellstart[NB][NCELL], g_cellcur[NB][NCELL];
__device__ int g_nvalid[NB];
__device__ float g_txx[NB][NPTS], g_txy[NB][NPTS], g_txz[NB][NPTS]; // transposed: [p*512+c]
__device__ unsigned short g_perm[NB][NPTS];
__device__ float4 g_meta[NB][NCHK];
__device__ float g_cx[NB][MC3], g_cy[NB][MC3], g_cz[NB][MC3];
__device__ float g_kpx[NB][NKP], g_kpy[NB][NKP], g_kpz[NB][NKP];
__device__ float g_fraw[NB * NPTS * CRAW];
__device__ float g_fc3[NB * MC3 * CC3];
__device__ float g_feats[NB * NKP * CF];

// ---------------- 1) SoA copy + ROI validity + cell id ----------------------
__global__ void prep_points_kernel(const float* __restrict__ points,
                                   const float* __restrict__ bboxes) {
    int tid = blockIdx.x * blockDim.x + threadIdx.x;
    if (tid >= NB * NPTS) return;
    int b = tid / NPTS, i = tid % NPTS;
    const float* p = points + (size_t)tid * 5;
    float x = p[0], y = p[1], z = p[2];
    g_px[b][i] = x; g_py[b][i] = y; g_pz[b][i] = z;

    float best = 3.0e38f;
    int bidx = 0;
    const float* bb0 = bboxes + (size_t)b * NROI * 7;
    for (int r = 0; r < NROI; ++r) {
        const float* bb = bb0 + r * 7;
        float dx = x - bb[0], dy = y - bb[1], dz = z - bb[2];
        float d = __fsqrt_rn(dx * dx + dy * dy + dz * dz);
        if (d < best) { best = d; bidx = r; }
    }
    const float* bb = bb0 + bidx * 7;
    float hx = bb[3] * 0.5f, hy = bb[4] * 0.5f, hz = bb[5] * 0.5f;
    float rm = __fsqrt_rn(hx * hx + hy * hy + hz * hz);
    g_valid[b][i] = (best < rm + 2.4f) ? 1 : 0;

    const float inv = (float)GRIDC / 150.4f;
    int cx = min(GRIDC - 1, max(0, (int)((x + 75.2f) * inv)));
    int cy = min(GRIDC - 1, max(0, (int)((y + 75.2f) * inv)));
    g_cell[b][i] = (unsigned short)(cy * GRIDC + cx);
}

__global__ void prep_c3_kernel(const float* __restrict__ conv3) {
    int tid = blockIdx.x * blockDim.x + threadIdx.x;
    if (tid >= NB * MC3) return;
    int b = tid / MC3, i = tid % MC3;
    const float* p = conv3 + (size_t)tid * 67;
    g_cx[b][i] = p[0]; g_cy[b][i] = p[1]; g_cz[b][i] = p[2];
}

// ---------------- 2) cell histogram + scan (one block per batch) ------------
__global__ void histscan_kernel() {
    __shared__ int h[NCELL];
    __shared__ int sa[NCELL], sb[NCELL];
    int b = blockIdx.x, t = threadIdx.x;   // 576 threads
    h[t] = 0;
    __syncthreads();
    for (int i = t; i < NPTS; i += NCELL)
        if (g_valid[b][i]) atomicAdd(&h[g_cell[b][i]], 1);
    __syncthreads();
    sa[t] = h[t];
    __syncthreads();
    int* src = sa; int* dst = sb;
    for (int off = 1; off < NCELL; off <<= 1) {
        int v = src[t];
        if (t >= off) v += src[t - off];
        dst[t] = v;
        __syncthreads();
        int* tmp = src; src = dst; dst = tmp;
    }
    int incl = src[t];
    int start = incl - h[t];
    g_cellstart[b][t] = start;
    g_cellcur[b][t] = start;
    if (t == NCELL - 1) g_nvalid[b] = incl;
}

// ---------------- 3a) zero-fill transposed arrays (pad safety) --------------
__global__ void padfill_kernel() {
    int tid = blockIdx.x * blockDim.x + threadIdx.x;
    if (tid >= NB * NPTS) return;
    int b = tid / NPTS, i = tid % NPTS;
    g_txx[b][i] = 0.0f; g_txy[b][i] = 0.0f; g_txz[b][i] = 0.0f;
}

// ---------------- 3b) scatter valid points into transposed sorted order -----
__global__ void scatter_kernel() {
    int tid = blockIdx.x * blockDim.x + threadIdx.x;
    if (tid >= NB * NPTS) return;
    int b = tid / NPTS, i = tid % NPTS;
    if (!g_valid[b][i]) return;
    int cell = g_cell[b][i];
    int pos = atomicAdd(&g_cellcur[b][cell], 1);
    int tpos = ((pos & 31) << 9) | (pos >> 5);   // [point][chunk], 512 chunks
    g_txx[b][tpos] = g_px[b][i];
    g_txy[b][tpos] = g_py[b][i];
    g_txz[b][tpos] = g_pz[b][i];
    g_perm[b][pos] = (unsigned short)i;
}

// ---------------- 4) per-chunk bounding spheres (thread per chunk) ----------
__global__ void bounds_kernel() {
    int idx = blockIdx.x * 256 + threadIdx.x;   // NB*512 threads
    if (idx >= NB * NCHK) return;
    int b = idx >> 9, c = idx & (NCHK - 1);
    int n = g_nvalid[b];
    int sz = min(32, n - 32 * c);
    float4 out;
    if (sz <= 0) {
        out = make_float4(1.0e8f, 1.0e8f, 1.0e8f, 0.0f);
    } else {
        float xn = 3.0e38f, xm = -3.0e38f;
        float yn = 3.0e38f, ym = -3.0e38f;
        float zn = 3.0e38f, zm = -3.0e38f;
        for (int p = 0; p < sz; ++p) {
            float x = g_txx[b][p * 512 + c];
            float y = g_txy[b][p * 512 + c];
            float z = g_txz[b][p * 512 + c];
            xn = fminf(xn, x); xm = fmaxf(xm, x);
            yn = fminf(yn, y); ym = fmaxf(ym, y);
            zn = fminf(zn, z); zm = fmaxf(zm, z);
        }
        float ccx = (xn + xm) * 0.5f, ccy = (yn + ym) * 0.5f, ccz = (zn + zm) * 0.5f;
        float m2 = 0.0f;
        for (int p = 0; p < sz; ++p) {
            float dx = g_txx[b][p * 512 + c] - ccx;
            float dy = g_txy[b][p * 512 + c] - ccy;
            float dz = g_txz[b][p * 512 + c] - ccz;
            m2 = fmaxf(m2, dx * dx + dy * dy + dz * dz);
        }
        float r = __fsqrt_rn(m2);
        out = make_float4(ccx, ccy, ccz, r * 1.00002f + 1.0e-3f);
    }
    g_meta[b][c] = out;
}

// ---------------- 5) per-point MLPs -----------------------------------------
__global__ void fraw_kernel(const float* __restrict__ points,
                            const float* __restrict__ W,
                            const float* __restrict__ bias) {
    int tid = blockIdx.x * blockDim.x + threadIdx.x;
    if (tid >= NB * NPTS * CRAW) return;
    int c = tid & (CRAW - 1);
    int pi = tid >> 5;
    const float* p = points + (size_t)pi * 5;
    float v = p[3] * W[c] + p[4] * W[CRAW + c] + bias[c];
    g_fraw[tid] = fmaxf(v, 0.0f);
}

__global__ void fc3_kernel(const float* __restrict__ conv3,
                           const float* __restrict__ W,
                           const float* __restrict__ bias) {
    int tid = blockIdx.x * blockDim.x + threadIdx.x;
    if (tid >= NB * MC3 * CC3) return;
    int c = tid & (CC3 - 1);
    int pi = tid >> 6;
    const float* p = conv3 + (size_t)pi * 67 + 3;
    float acc = 0.0f;
    #pragma unroll 8
    for (int k = 0; k < CC3; ++k) acc += p[k] * W[k * CC3 + c];
    g_fc3[tid] = fmaxf(acc + bias[c], 0.0f);
}

// ---------------- 6) chunk-per-thread FPS with incremental argmax pairs -----
// 512 threads; thread t owns chunk t (sorted points 32t..32t+31), coords in
// transposed smem [p*512+t] (conflict-free), dd[32] static registers.
// Thread maintains packed pair (fkey(chunkmax)<<32 | (0x3fff-minorig)<<14 | sp)
// updated ONLY when the chunk is updated. Per-iteration fixed path: 2 REDUX +
// 1 smem write per warp, bar, warp0 reduces 16 pairs + publishes, bar. No
// rescans, no atomics. Exact: max value then min ORIGINAL index == jnp.argmax.
__global__ void __launch_bounds__(512, 1) fps_kernel() {
    extern __shared__ float smem[];
    float* s_x = smem;            // [32][512] transposed
    float* s_y = smem + NPTS;
    float* s_z = smem + 2 * NPTS;
    __shared__ ull s_pairs[16];
    __shared__ float s_kx, s_ky, s_kz;

    int b = blockIdx.x, t = threadIdx.x;
    int w = t >> 5, j = t & 31;
    int n = g_nvalid[b];

    for (int i = t; i < NPTS; i += 512) {
        s_x[i] = g_txx[b][i];
        s_y[i] = g_txy[b][i];
        s_z[i] = g_txz[b][i];
    }
    // 32 orig indices of this chunk, packed 2x16-bit per register
    unsigned pr[16];
    {
        const uint4* pp = (const uint4*)(&g_perm[b][32 * t]);
        #pragma unroll
        for (int q = 0; q < 4; ++q) {
            uint4 v = pp[q];
            pr[4 * q + 0] = v.x; pr[4 * q + 1] = v.y;
            pr[4 * q + 2] = v.z; pr[4 * q + 3] = v.w;
        }
    }
    float4 mt = g_meta[b][t];

    float dd[32];
    #pragma unroll
    for (int p = 0; p < 32; ++p)
        dd[p] = (32 * t + p < n) ? 1.0e10f : -1.0e10f;

    // initial pair: (max value, min orig index among exact max, sorted pos)
    float vm = dd[0];
    #pragma unroll
    for (int p = 1; p < 32; ++p) vm = fmaxf(vm, dd[p]);
    unsigned bo = 0xffffu; int bp = 0;
    #pragma unroll
    for (int p = 0; p < 32; ++p) {
        if (dd[p] == vm) {
            unsigned o = (pr[p >> 1] >> (16 * (p & 1))) & 0xffffu;
            if (o < bo) { bo = o; bp = p; }
        }
    }
    ull pair = ((ull)fkey(vm) << 32)
             | ((ull)((0x3fffu - bo) & 0x3fffu) << 14)
             | (ull)(32 * t + bp);
    __syncthreads();

    for (int it = 0; it < NKP; ++it) {
        // ---- warp reduce of 64-bit pair via key/lo REDUX split ----
        unsigned hk = (unsigned)(pair >> 32);
        unsigned wk = __reduce_max_sync(FULLM, hk);
        unsigned lo = (hk == wk) ? (unsigned)pair : 0u;
        lo = __reduce_max_sync(FULLM, lo);
        if (j == 0) s_pairs[w] = ((ull)wk << 32) | lo;
        __syncthreads();                                   // bar A

        // ---- warp 0: block reduce + publish winner ----
        if (w == 0) {
            ull p2 = (j < 16) ? s_pairs[j] : 0ull;
            unsigned hk2 = (unsigned)(p2 >> 32);
            unsigned wk2 = __reduce_max_sync(FULLM, hk2);
            unsigned lo2 = (hk2 == wk2) ? (unsigned)p2 : 0u;
            lo2 = __reduce_max_sync(FULLM, lo2);
            if (j == 0) {
                int sp = (int)(lo2 & 0x3fffu);
                int tp = ((sp & 31) << 9) | (sp >> 5);     // transposed index
                float x = s_x[tp], y = s_y[tp], z = s_z[tp];
                s_kx = x; s_ky = y; s_kz = z;
                g_kpx[b][it] = x; g_kpy[b][it] = y; g_kpz[b][it] = z;
            }
        }
        __syncthreads();                                   // bar B
        if (it == NKP - 1) break;
        float kx = s_kx, ky = s_ky, kz = s_kz;

        // ---- pruned update (per-thread; pair recomputed only here) ----
        float dxc = kx - mt.x, dyc = ky - mt.y, dzc = kz - mt.z;
        float dc = __fsqrt_rn(dxc * dxc + dyc * dyc + dzc * dzc);
        float lhs = dc - mt.w - 1.0e-3f;
        if (!((lhs > 0.0f) && (lhs * lhs * 0.99999f > vm))) {
            float nvm = -3.0e38f;
            #pragma unroll
            for (int p = 0; p < 32; ++p) {
                int tp = p * 512 + t;
                float dx = s_x[tp] - kx;
                float dy = s_y[tp] - ky;
                float dz = s_z[tp] - kz;
                float nd = fmaf(dz, dz, fmaf(dy, dy, dx * dx));
                float v = fminf(dd[p], nd);
                dd[p] = v;
                nvm = fmaxf(nvm, v);
            }
            vm = nvm;
            unsigned nbo = 0xffffu; int nbp = 0;
            #pragma unroll
            for (int p = 0; p < 32; ++p) {
                if (dd[p] == vm) {
                    unsigned o = (pr[p >> 1] >> (16 * (p & 1))) & 0xffffu;
                    if (o < nbo) { nbo = o; nbp = p; }
                }
            }
            pair = ((ull)fkey(vm) << 32)
                 | ((ull)((0x3fffu - nbo) & 0x3fffu) << 14)
                 | (ull)(32 * t + nbp);
        }
    }
}

// ---------------- 7) bilinear BEV sampling ----------------------------------
__global__ void bev_kernel(const float* __restrict__ sf) {
    int k = blockIdx.x, b = blockIdx.y, c = threadIdx.x;
    float kx = g_kpx[b][k], ky = g_kpy[b][k];
    float xi = __fdiv_rn(__fdiv_rn(kx - (-75.2f), 0.1f), 8.0f);
    float yi = __fdiv_rn(__fdiv_rn(ky - (-75.2f), 0.1f), 8.0f);
    int x0 = min(max((int)floorf(xi), 0), HW - 1);
    int x1 = min(x0 + 1, HW - 1);
    int y0 = min(max((int)floorf(yi), 0), HW - 1);
    int y1 = min(y0 + 1, HW - 1);
    float xf0 = (float)x0, xf1 = (float)x1, yf0 = (float)y0, yf1 = (float)y1;
    float wa = (xf1 - xi) * (yf1 - yi);
    float wb = (xf1 - xi) * (yi - yf0);
    float wc = (xi - xf0) * (yf1 - yi);
    float wd = (xi - xf0) * (yi - yf0);
    const float* im = sf + ((size_t)b * CBEV + c) * (HW * HW);
    float Ia = im[y0 * HW + x0];
    float Ib = im[y1 * HW + x0];
    float Ic = im[y0 * HW + x1];
    float Id = im[y1 * HW + x1];
    g_feats[((size_t)b * NKP + k) * CF + c] = Ia * wa + Ib * wb + Ic * wc + Id * wd;
}

// ---------------- 8) radius aggregation (ballot-broadcast) ------------------
__global__ void agg_raw_kernel(float r2) {
    int b = blockIdx.y;
    int warp = threadIdx.x >> 5, lane = threadIdx.x & 31;
    int k = blockIdx.x * 8 + warp;
    float kx = g_kpx[b][k], ky = g_kpy[b][k], kz = g_kpz[b][k];
    float acc = 0.0f;
    int cnt = 0;
    __shared__ float sx[256], sy[256], sz[256];
    for (int base = 0; base < NPTS; base += 256) {
        __syncthreads();
        int i = base + threadIdx.x;
        sx[threadIdx.x] = g_px[b][i];
        sy[threadIdx.x] = g_py[b][i];
        sz[threadIdx.x] = g_pz[b][i];
        __syncthreads();
        #pragma unroll
        for (int s = 0; s < 8; ++s) {
            int jj = s * 32 + lane;
            float dx = sx[jj] - kx, dy = sy[jj] - ky, dz = sz[jj] - kz;
            float d2 = dx * dx + dy * dy + dz * dz;
            unsigned m = __ballot_sync(FULLM, d2 < r2);
            while (m) {
                int src = __ffs(m) - 1;
                m &= m - 1;
                int gp = base + s * 32 + src;
                acc += g_fraw[((size_t)b * NPTS + gp) * CRAW + lane];
                cnt++;
            }
        }
    }
    float c = fmaxf((float)cnt, 1.0f);
    g_feats[((size_t)b * NKP + k) * CF + CBEV + lane] = acc / c;
}

__global__ void agg_c3_kernel(float r2) {
    int b = blockIdx.y;
    int warp = threadIdx.x >> 5, lane = threadIdx.x & 31;
    int k = blockIdx.x * 8 + warp;
    float kx = g_kpx[b][k], ky = g_kpy[b][k], kz = g_kpz[b][k];
    float acc0 = 0.0f, acc1 = 0.0f;
    int cnt = 0;
    __shared__ float sx[256], sy[256], sz[256];
    for (int base = 0; base < MC3; base += 256) {
        __syncthreads();
        int i = base + threadIdx.x;
        sx[threadIdx.x] = g_cx[b][i];
        sy[threadIdx.x] = g_cy[b][i];
        sz[threadIdx.x] = g_cz[b][i];
        __syncthreads();
        #pragma unroll
        for (int s = 0; s < 8; ++s) {
            int jj = s * 32 + lane;
            float dx = sx[jj] - kx, dy = sy[jj] - ky, dz = sz[jj] - kz;
            float d2 = dx * dx + dy * dy + dz * dz;
            unsigned m = __ballot_sync(FULLM, d2 < r2);
            while (m) {
                int src = __ffs(m) - 1;
                m &= m - 1;
                int gp = base + s * 32 + src;
                const float* fp = g_fc3 + ((size_t)b * MC3 + gp) * CC3;
                acc0 += fp[lane];
                acc1 += fp[lane + 32];
                cnt++;
            }
        }
    }
    float c = fmaxf((float)cnt, 1.0f);
    float* o = g_feats + ((size_t)b * NKP + k) * CF + CBEV + CRAW;
    o[lane] = acc0 / c;
    o[lane + 32] = acc1 / c;
}

// ---------------- 9) fuse GEMM + BN + ReLU ----------------------------------
#define ROWS_PB 16
__global__ void fuse_kernel(const float* __restrict__ W,
                            const float* __restrict__ gamma,
                            const float* __restrict__ beta,
                            const float* __restrict__ mean,
                            const float* __restrict__ var,
                            float* __restrict__ out) {
    __shared__ float sf[ROWS_PB][CF];
    int row0 = blockIdx.x * ROWS_PB;
    int tid = threadIdx.x;
    for (int idx = tid; idx < ROWS_PB * CF; idx += 128) {
        ((float*)sf)[idx] = g_feats[(size_t)row0 * CF + idx];
    }
    __syncthreads();
    int c = tid;
    float acc[ROWS_PB];
    #pragma unroll
    for (int r = 0; r < ROWS_PB; ++r) acc[r] = 0.0f;
    for (int k = 0; k < CF; ++k) {
        float wv = W[k * COUT + c];
        #pragma unroll
        for (int r = 0; r < ROWS_PB; ++r) acc[r] += sf[r][k] * wv;
    }
    float mu = mean[c];
    float iv = rsqrtf(var[c] + 1e-5f);
    float g = gamma[c], be = beta[c];
    #pragma unroll
    for (int r = 0; r < ROWS_PB; ++r) {
        float v = (acc[r] - mu) * iv * g + be;
        out[(size_t)(row0 + r) * COUT + c] = fmaxf(v, 0.0f);
    }
}

// ---------------- 10) keypoints output --------------------------------------
__global__ void kpout_kernel(float* __restrict__ out) {
    int tid = blockIdx.x * blockDim.x + threadIdx.x;
    if (tid >= NB * NKP * 3) return;
    int b = tid / (NKP * 3);
    int rem = tid % (NKP * 3);
    int k = rem / 3, d = rem % 3;
    float v = (d == 0) ? g_kpx[b][k] : (d == 1 ? g_kpy[b][k] : g_kpz[b][k]);
    out[(size_t)NB * NKP * COUT + tid] = v;
}

// ---------------- launcher ---------------------------------------------------
extern "C" void kernel_launch(void* const* d_in, const int* in_sizes, int n_in,
                              void* d_out, int out_size) {
    const float* points  = (const float*)d_in[0];
    const float* bboxes  = (const float*)d_in[1];
    const float* spatial = (const float*)d_in[2];
    const float* conv3   = (const float*)d_in[3];
    const float* W_raw   = (const float*)d_in[4];
    const float* b_raw   = (const float*)d_in[5];
    const float* W_c3    = (const float*)d_in[6];
    const float* b_c3    = (const float*)d_in[7];
    const float* W_fuse  = (const float*)d_in[8];
    const float* bn_g    = (const float*)d_in[9];
    const float* bn_b    = (const float*)d_in[10];
    const float* bn_m    = (const float*)d_in[11];
    const float* bn_v    = (const float*)d_in[12];
    float* out = (float*)d_out;

    const int fps_smem = 3 * NPTS * (int)sizeof(float);   // 196608 B
    cudaFuncSetAttribute(fps_kernel, cudaFuncAttributeMaxDynamicSharedMemorySize,
                         fps_smem);

    prep_points_kernel<<<(NB * NPTS + 255) / 256, 256>>>(points, bboxes);
    prep_c3_kernel<<<(NB * MC3 + 255) / 256, 256>>>(conv3);
    histscan_kernel<<<NB, NCELL>>>();
    padfill_kernel<<<(NB * NPTS + 255) / 256, 256>>>();
    scatter_kernel<<<(NB * NPTS + 255) / 256, 256>>>();
    bounds_kernel<<<(NB * NCHK + 255) / 256, 256>>>();
    fraw_kernel<<<(NB * NPTS * CRAW + 255) / 256, 256>>>(points, W_raw, b_raw);
    fc3_kernel<<<(NB * MC3 * CC3 + 255) / 256, 256>>>(conv3, W_c3, b_c3);
    fps_kernel<<<NB, 512, fps_smem>>>();
    bev_kernel<<<dim3(NKP, NB), CBEV>>>(spatial);
    agg_raw_kernel<<<dim3(NKP / 8, NB), 256>>>(0.8f * 0.8f);
    agg_c3_kernel<<<dim3(NKP / 8, NB), 256>>>(1.6f * 1.6f);
    fuse_kernel<<<(NB * NKP) / ROWS_PB, COUT>>>(W_fuse, bn_g, bn_b, bn_m, bn_v, out);
    kpout_kernel<<<(NB * NKP * 3 + 255) / 256, 256>>>(out);
}

// round 11
// speedup vs baseline: 1.7530x; 1.0255x over previous
#include <cuda_runtime.h>
#include <cstdint>

#define NB    2
#define NPTS  16384
#define MC3   8192
#define NROI  128
#define NKP   2048
#define CBEV  256
#define CRAW  32
#define CC3   64
#define CF    (CBEV + CRAW + CC3)   // 352
#define COUT  128
#define HW    188
#define GRIDC 24
#define NCELL (GRIDC * GRIDC)       // 576
#define NCHK  512                   // 32-point chunks
#define FULLM 0xffffffffu

typedef unsigned long long ull;

// monotonic float <-> uint key (total order; umax on key == fmax)
__device__ __forceinline__ unsigned fkey(float f) {
    unsigned b = __float_as_uint(f);
    return b ^ ((unsigned)((int)b >> 31) | 0x80000000u);
}

// ---------------- scratch (device globals; no allocation allowed) -----------
__device__ float g_px[NB][NPTS], g_py[NB][NPTS], g_pz[NB][NPTS];
__device__ unsigned char g_valid[NB][NPTS];
__device__ unsigned short g_cell[NB][NPTS];
__device__ int g_cellstart[NB][NCELL], g_cellcur[NB][NCELL];
__device__ int g_nvalid[NB];
__device__ float g_txx[NB][NPTS], g_txy[NB][NPTS], g_txz[NB][NPTS]; // transposed: [p*512+c]
__device__ unsigned short g_perm[NB][NPTS];
__device__ float4 g_meta[NB][NCHK];
__device__ float g_cx[NB][MC3], g_cy[NB][MC3], g_cz[NB][MC3];
__device__ float g_kpx[NB][NKP], g_kpy[NB][NKP], g_kpz[NB][NKP];
__device__ float g_fraw[NB * NPTS * CRAW];
__device__ float g_fc3[NB * MC3 * CC3];
__device__ float g_feats[NB * NKP * CF];

// ---------------- 1) SoA copy + ROI validity + cell id ----------------------
__global__ void prep_points_kernel(const float* __restrict__ points,
                                   const float* __restrict__ bboxes) {
    int tid = blockIdx.x * blockDim.x + threadIdx.x;
    if (tid >= NB * NPTS) return;
    int b = tid / NPTS, i = tid % NPTS;
    const float* p = points + (size_t)tid * 5;
    float x = p[0], y = p[1], z = p[2];
    g_px[b][i] = x; g_py[b][i] = y; g_pz[b][i] = z;

    float best = 3.0e38f;
    int bidx = 0;
    const float* bb0 = bboxes + (size_t)b * NROI * 7;
    for (int r = 0; r < NROI; ++r) {
        const float* bb = bb0 + r * 7;
        float dx = x - bb[0], dy = y - bb[1], dz = z - bb[2];
        float d = __fsqrt_rn(dx * dx + dy * dy + dz * dz);
        if (d < best) { best = d; bidx = r; }
    }
    const float* bb = bb0 + bidx * 7;
    float hx = bb[3] * 0.5f, hy = bb[4] * 0.5f, hz = bb[5] * 0.5f;
    float rm = __fsqrt_rn(hx * hx + hy * hy + hz * hz);
    g_valid[b][i] = (best < rm + 2.4f) ? 1 : 0;

    const float inv = (float)GRIDC / 150.4f;
    int cx = min(GRIDC - 1, max(0, (int)((x + 75.2f) * inv)));
    int cy = min(GRIDC - 1, max(0, (int)((y + 75.2f) * inv)));
    g_cell[b][i] = (unsigned short)(cy * GRIDC + cx);
}

__global__ void prep_c3_kernel(const float* __restrict__ conv3) {
    int tid = blockIdx.x * blockDim.x + threadIdx.x;
    if (tid >= NB * MC3) return;
    int b = tid / MC3, i = tid % MC3;
    const float* p = conv3 + (size_t)tid * 67;
    g_cx[b][i] = p[0]; g_cy[b][i] = p[1]; g_cz[b][i] = p[2];
}

// ---------------- 2) cell histogram + scan (one block per batch) ------------
__global__ void histscan_kernel() {
    __shared__ int h[NCELL];
    __shared__ int sa[NCELL], sb[NCELL];
    int b = blockIdx.x, t = threadIdx.x;   // 576 threads
    h[t] = 0;
    __syncthreads();
    for (int i = t; i < NPTS; i += NCELL)
        if (g_valid[b][i]) atomicAdd(&h[g_cell[b][i]], 1);
    __syncthreads();
    sa[t] = h[t];
    __syncthreads();
    int* src = sa; int* dst = sb;
    for (int off = 1; off < NCELL; off <<= 1) {
        int v = src[t];
        if (t >= off) v += src[t - off];
        dst[t] = v;
        __syncthreads();
        int* tmp = src; src = dst; dst = tmp;
    }
    int incl = src[t];
    int start = incl - h[t];
    g_cellstart[b][t] = start;
    g_cellcur[b][t] = start;
    if (t == NCELL - 1) g_nvalid[b] = incl;
}

// ---------------- 3a) zero-fill transposed arrays (pad safety) --------------
__global__ void padfill_kernel() {
    int tid = blockIdx.x * blockDim.x + threadIdx.x;
    if (tid >= NB * NPTS) return;
    int b = tid / NPTS, i = tid % NPTS;
    g_txx[b][i] = 0.0f; g_txy[b][i] = 0.0f; g_txz[b][i] = 0.0f;
}

// ---------------- 3b) scatter valid points into transposed sorted order -----
__global__ void scatter_kernel() {
    int tid = blockIdx.x * blockDim.x + threadIdx.x;
    if (tid >= NB * NPTS) return;
    int b = tid / NPTS, i = tid % NPTS;
    if (!g_valid[b][i]) return;
    int cell = g_cell[b][i];
    int pos = atomicAdd(&g_cellcur[b][cell], 1);
    int tpos = ((pos & 31) << 9) | (pos >> 5);   // [point][chunk], 512 chunks
    g_txx[b][tpos] = g_px[b][i];
    g_txy[b][tpos] = g_py[b][i];
    g_txz[b][tpos] = g_pz[b][i];
    g_perm[b][pos] = (unsigned short)i;
}

// ---------------- 4) per-chunk bounding spheres (thread per chunk) ----------
__global__ void bounds_kernel() {
    int idx = blockIdx.x * 256 + threadIdx.x;   // NB*512 threads
    if (idx >= NB * NCHK) return;
    int b = idx >> 9, c = idx & (NCHK - 1);
    int n = g_nvalid[b];
    int sz = min(32, n - 32 * c);
    float4 out;
    if (sz <= 0) {
        out = make_float4(1.0e8f, 1.0e8f, 1.0e8f, 0.0f);
    } else {
        float xn = 3.0e38f, xm = -3.0e38f;
        float yn = 3.0e38f, ym = -3.0e38f;
        float zn = 3.0e38f, zm = -3.0e38f;
        for (int p = 0; p < sz; ++p) {
            float x = g_txx[b][p * 512 + c];
            float y = g_txy[b][p * 512 + c];
            float z = g_txz[b][p * 512 + c];
            xn = fminf(xn, x); xm = fmaxf(xm, x);
            yn = fminf(yn, y); ym = fmaxf(ym, y);
            zn = fminf(zn, z); zm = fmaxf(zm, z);
        }
        float ccx = (xn + xm) * 0.5f, ccy = (yn + ym) * 0.5f, ccz = (zn + zm) * 0.5f;
        float m2 = 0.0f;
        for (int p = 0; p < sz; ++p) {
            float dx = g_txx[b][p * 512 + c] - ccx;
            float dy = g_txy[b][p * 512 + c] - ccy;
            float dz = g_txz[b][p * 512 + c] - ccz;
            m2 = fmaxf(m2, dx * dx + dy * dy + dz * dz);
        }
        float r = __fsqrt_rn(m2);
        out = make_float4(ccx, ccy, ccz, r * 1.00002f + 1.0e-3f);
    }
    g_meta[b][c] = out;
}

// ---------------- 5) per-point MLPs -----------------------------------------
__global__ void fraw_kernel(const float* __restrict__ points,
                            const float* __restrict__ W,
                            const float* __restrict__ bias) {
    int tid = blockIdx.x * blockDim.x + threadIdx.x;
    if (tid >= NB * NPTS * CRAW) return;
    int c = tid & (CRAW - 1);
    int pi = tid >> 5;
    const float* p = points + (size_t)pi * 5;
    float v = p[3] * W[c] + p[4] * W[CRAW + c] + bias[c];
    g_fraw[tid] = fmaxf(v, 0.0f);
}

__global__ void fc3_kernel(const float* __restrict__ conv3,
                           const float* __restrict__ W,
                           const float* __restrict__ bias) {
    int tid = blockIdx.x * blockDim.x + threadIdx.x;
    if (tid >= NB * MC3 * CC3) return;
    int c = tid & (CC3 - 1);
    int pi = tid >> 6;
    const float* p = conv3 + (size_t)pi * 67 + 3;
    float acc = 0.0f;
    #pragma unroll 8
    for (int k = 0; k < CC3; ++k) acc += p[k] * W[k * CC3 + c];
    g_fc3[tid] = fmaxf(acc + bias[c], 0.0f);
}

// ---------------- 6) single-barrier FPS (redundant block-reduce) -------------
// 512 threads; thread t owns chunk t. dd[32] static registers, coords in
// transposed smem [p*512+t]. Persistent s_pairs[16]: warp w's max pair.
// Per iteration: EVERY warp redundantly reduces the 16 pairs (winner's sorted
// pos is encoded in the pair; coords come from read-only smem -> no publish,
// no second barrier). After update, only CHANGED warps re-reduce + rewrite
// their slot. ONE __syncthreads per iteration.
// Pair = fkey(chunkmax)<<32 | (0x3fff - minorig)<<14 | sortedpos
//  -> max pair == (max value, then min ORIGINAL index) == jnp.argmax.
__global__ void __launch_bounds__(512, 1) fps_kernel() {
    extern __shared__ float smem[];
    float* s_x = smem;            // [32][512] transposed
    float* s_y = smem + NPTS;
    float* s_z = smem + 2 * NPTS;
    __shared__ ull s_pairs[16];

    int b = blockIdx.x, t = threadIdx.x;
    int w = t >> 5, j = t & 31;
    int n = g_nvalid[b];

    for (int i = t; i < NPTS; i += 512) {
        s_x[i] = g_txx[b][i];
        s_y[i] = g_txy[b][i];
        s_z[i] = g_txz[b][i];
    }
    // 32 orig indices of this chunk, packed 2x16-bit per register
    unsigned pr[16];
    {
        const uint4* pp = (const uint4*)(&g_perm[b][32 * t]);
        #pragma unroll
        for (int q = 0; q < 4; ++q) {
            uint4 v = pp[q];
            pr[4 * q + 0] = v.x; pr[4 * q + 1] = v.y;
            pr[4 * q + 2] = v.z; pr[4 * q + 3] = v.w;
        }
    }
    float4 mt = g_meta[b][t];

    float dd[32];
    #pragma unroll
    for (int p = 0; p < 32; ++p)
        dd[p] = (32 * t + p < n) ? 1.0e10f : -1.0e10f;

    // initial pair
    float vm = dd[0];
    #pragma unroll
    for (int p = 1; p < 32; ++p) vm = fmaxf(vm, dd[p]);
    unsigned bo = 0xffffu; int bp = 0;
    #pragma unroll
    for (int p = 0; p < 32; ++p) {
        if (dd[p] == vm) {
            unsigned o = (pr[p >> 1] >> (16 * (p & 1))) & 0xffffu;
            if (o < bo) { bo = o; bp = p; }
        }
    }
    ull pair = ((ull)fkey(vm) << 32)
             | ((ull)((0x3fffu - bo) & 0x3fffu) << 14)
             | (ull)(32 * t + bp);

    // initial warp reduce -> s_pairs[w]
    {
        unsigned hk = (unsigned)(pair >> 32);
        unsigned wk = __reduce_max_sync(FULLM, hk);
        unsigned lo = (hk == wk) ? (unsigned)pair : 0u;
        lo = __reduce_max_sync(FULLM, lo);
        if (j == 0) s_pairs[w] = ((ull)wk << 32) | lo;
    }
    __syncthreads();

    for (int it = 0; it < NKP; ++it) {
        // ---- redundant block reduce in every warp (no publish needed) ----
        ull p2 = s_pairs[j & 15];
        unsigned hk2 = (unsigned)(p2 >> 32);
        unsigned wk2 = __reduce_max_sync(FULLM, hk2);
        unsigned lo2 = (hk2 == wk2) ? (unsigned)p2 : 0u;
        lo2 = __reduce_max_sync(FULLM, lo2);
        int sp = (int)(lo2 & 0x3fffu);
        int tp = ((sp & 31) << 9) | (sp >> 5);        // transposed index
        float kx = s_x[tp], ky = s_y[tp], kz = s_z[tp];  // broadcast LDS
        if (t == 0) { g_kpx[b][it] = kx; g_kpy[b][it] = ky; g_kpz[b][it] = kz; }
        if (it == NKP - 1) break;

        // ---- pruned update ----
        float dxc = kx - mt.x, dyc = ky - mt.y, dzc = kz - mt.z;
        float dc = __fsqrt_rn(dxc * dxc + dyc * dyc + dzc * dzc);
        float lhs = dc - mt.w - 1.0e-3f;
        bool changed = !((lhs > 0.0f) && (lhs * lhs * 0.99999f > vm));
        if (changed) {
            float nvm = -3.0e38f;
            #pragma unroll
            for (int p = 0; p < 32; ++p) {
                int ti = p * 512 + t;
                float dx = s_x[ti] - kx;
                float dy = s_y[ti] - ky;
                float dz = s_z[ti] - kz;
                float nd = fmaf(dz, dz, fmaf(dy, dy, dx * dx));
                float v = fminf(dd[p], nd);
                dd[p] = v;
                nvm = fmaxf(nvm, v);
            }
            vm = nvm;
            unsigned nbo = 0xffffu; int nbp = 0;
            #pragma unroll
            for (int p = 0; p < 32; ++p) {
                if (dd[p] == vm) {
                    unsigned o = (pr[p >> 1] >> (16 * (p & 1))) & 0xffffu;
                    if (o < nbo) { nbo = o; nbp = p; }
                }
            }
            pair = ((ull)fkey(vm) << 32)
                 | ((ull)((0x3fffu - nbo) & 0x3fffu) << 14)
                 | (ull)(32 * t + nbp);
        }
        // ---- only changed warps re-reduce + rewrite their slot ----
        if (__ballot_sync(FULLM, changed)) {
            unsigned hk = (unsigned)(pair >> 32);
            unsigned wk = __reduce_max_sync(FULLM, hk);
            unsigned lo = (hk == wk) ? (unsigned)pair : 0u;
            lo = __reduce_max_sync(FULLM, lo);
            if (j == 0) s_pairs[w] = ((ull)wk << 32) | lo;
        }
        __syncthreads();                               // the ONLY barrier
    }
}

// ---------------- 7) bilinear BEV sampling ----------------------------------
__global__ void bev_kernel(const float* __restrict__ sf) {
    int k = blockIdx.x, b = blockIdx.y, c = threadIdx.x;
    float kx = g_kpx[b][k], ky = g_kpy[b][k];
    float xi = __fdiv_rn(__fdiv_rn(kx - (-75.2f), 0.1f), 8.0f);
    float yi = __fdiv_rn(__fdiv_rn(ky - (-75.2f), 0.1f), 8.0f);
    int x0 = min(max((int)floorf(xi), 0), HW - 1);
    int x1 = min(x0 + 1, HW - 1);
    int y0 = min(max((int)floorf(yi), 0), HW - 1);
    int y1 = min(y0 + 1, HW - 1);
    float xf0 = (float)x0, xf1 = (float)x1, yf0 = (float)y0, yf1 = (float)y1;
    float wa = (xf1 - xi) * (yf1 - yi);
    float wb = (xf1 - xi) * (yi - yf0);
    float wc = (xi - xf0) * (yf1 - yi);
    float wd = (xi - xf0) * (yi - yf0);
    const float* im = sf + ((size_t)b * CBEV + c) * (HW * HW);
    float Ia = im[y0 * HW + x0];
    float Ib = im[y1 * HW + x0];
    float Ic = im[y0 * HW + x1];
    float Id = im[y1 * HW + x1];
    g_feats[((size_t)b * NKP + k) * CF + c] = Ia * wa + Ib * wb + Ic * wc + Id * wd;
}

// ---------------- 8) radius aggregation (ballot-broadcast) ------------------
__global__ void agg_raw_kernel(float r2) {
    int b = blockIdx.y;
    int warp = threadIdx.x >> 5, lane = threadIdx.x & 31;
    int k = blockIdx.x * 8 + warp;
    float kx = g_kpx[b][k], ky = g_kpy[b][k], kz = g_kpz[b][k];
    float acc = 0.0f;
    int cnt = 0;
    __shared__ float sx[256], sy[256], sz[256];
    for (int base = 0; base < NPTS; base += 256) {
        __syncthreads();
        int i = base + threadIdx.x;
        sx[threadIdx.x] = g_px[b][i];
        sy[threadIdx.x] = g_py[b][i];
        sz[threadIdx.x] = g_pz[b][i];
        __syncthreads();
        #pragma unroll
        for (int s = 0; s < 8; ++s) {
            int jj = s * 32 + lane;
            float dx = sx[jj] - kx, dy = sy[jj] - ky, dz = sz[jj] - kz;
            float d2 = dx * dx + dy * dy + dz * dz;
            unsigned m = __ballot_sync(FULLM, d2 < r2);
            while (m) {
                int src = __ffs(m) - 1;
                m &= m - 1;
                int gp = base + s * 32 + src;
                acc += g_fraw[((size_t)b * NPTS + gp) * CRAW + lane];
                cnt++;
            }
        }
    }
    float c = fmaxf((float)cnt, 1.0f);
    g_feats[((size_t)b * NKP + k) * CF + CBEV + lane] = acc / c;
}

__global__ void agg_c3_kernel(float r2) {
    int b = blockIdx.y;
    int warp = threadIdx.x >> 5, lane = threadIdx.x & 31;
    int k = blockIdx.x * 8 + warp;
    float kx = g_kpx[b][k], ky = g_kpy[b][k], kz = g_kpz[b][k];
    float acc0 = 0.0f, acc1 = 0.0f;
    int cnt = 0;
    __shared__ float sx[256], sy[256], sz[256];
    for (int base = 0; base < MC3; base += 256) {
        __syncthreads();
        int i = base + threadIdx.x;
        sx[threadIdx.x] = g_cx[b][i];
        sy[threadIdx.x] = g_cy[b][i];
        sz[threadIdx.x] = g_cz[b][i];
        __syncthreads();
        #pragma unroll
        for (int s = 0; s < 8; ++s) {
            int jj = s * 32 + lane;
            float dx = sx[jj] - kx, dy = sy[jj] - ky, dz = sz[jj] - kz;
            float d2 = dx * dx + dy * dy + dz * dz;
            unsigned m = __ballot_sync(FULLM, d2 < r2);
            while (m) {
                int src = __ffs(m) - 1;
                m &= m - 1;
                int gp = base + s * 32 + src;
                const float* fp = g_fc3 + ((size_t)b * MC3 + gp) * CC3;
                acc0 += fp[lane];
                acc1 += fp[lane + 32];
                cnt++;
            }
        }
    }
    float c = fmaxf((float)cnt, 1.0f);
    float* o = g_feats + ((size_t)b * NKP + k) * CF + CBEV + CRAW;
    o[lane] = acc0 / c;
    o[lane + 32] = acc1 / c;
}

// ---------------- 9) fuse GEMM + BN + ReLU ----------------------------------
#define ROWS_PB 16
__global__ void fuse_kernel(const float* __restrict__ W,
                            const float* __restrict__ gamma,
                            const float* __restrict__ beta,
                            const float* __restrict__ mean,
                            const float* __restrict__ var,
                            float* __restrict__ out) {
    __shared__ float sf[ROWS_PB][CF];
    int row0 = blockIdx.x * ROWS_PB;
    int tid = threadIdx.x;
    for (int idx = tid; idx < ROWS_PB * CF; idx += 128) {
        ((float*)sf)[idx] = g_feats[(size_t)row0 * CF + idx];
    }
    __syncthreads();
    int c = tid;
    float acc[ROWS_PB];
    #pragma unroll
    for (int r = 0; r < ROWS_PB; ++r) acc[r] = 0.0f;
    for (int k = 0; k < CF; ++k) {
        float wv = W[k * COUT + c];
        #pragma unroll
        for (int r = 0; r < ROWS_PB; ++r) acc[r] += sf[r][k] * wv;
    }
    float mu = mean[c];
    float iv = rsqrtf(var[c] + 1e-5f);
    float g = gamma[c], be = beta[c];
    #pragma unroll
    for (int r = 0; r < ROWS_PB; ++r) {
        float v = (acc[r] - mu) * iv * g + be;
        out[(size_t)(row0 + r) * COUT + c] = fmaxf(v, 0.0f);
    }
}

// ---------------- 10) keypoints output --------------------------------------
__global__ void kpout_kernel(float* __restrict__ out) {
    int tid = blockIdx.x * blockDim.x + threadIdx.x;
    if (tid >= NB * NKP * 3) return;
    int b = tid / (NKP * 3);
    int rem = tid % (NKP * 3);
    int k = rem / 3, d = rem % 3;
    float v = (d == 0) ? g_kpx[b][k] : (d == 1 ? g_kpy[b][k] : g_kpz[b][k]);
    out[(size_t)NB * NKP * COUT + tid] = v;
}

// ---------------- launcher ---------------------------------------------------
extern "C" void kernel_launch(void* const* d_in, const int* in_sizes, int n_in,
                              void* d_out, int out_size) {
    const float* points  = (const float*)d_in[0];
    const float* bboxes  = (const float*)d_in[1];
    const float* spatial = (const float*)d_in[2];
    const float* conv3   = (const float*)d_in[3];
    const float* W_raw   = (const float*)d_in[4];
    const float* b_raw   = (const float*)d_in[5];
    const float* W_c3    = (const float*)d_in[6];
    const float* b_c3    = (const float*)d_in[7];
    const float* W_fuse  = (const float*)d_in[8];
    const float* bn_g    = (const float*)d_in[9];
    const float* bn_b    = (const float*)d_in[10];
    const float* bn_m    = (const float*)d_in[11];
    const float* bn_v    = (const float*)d_in[12];
    float* out = (float*)d_out;

    const int fps_smem = 3 * NPTS * (int)sizeof(float);   // 196608 B
    cudaFuncSetAttribute(fps_kernel, cudaFuncAttributeMaxDynamicSharedMemorySize,
                         fps_smem);

    prep_points_kernel<<<(NB * NPTS + 255) / 256, 256>>>(points, bboxes);
    prep_c3_kernel<<<(NB * MC3 + 255) / 256, 256>>>(conv3);
    histscan_kernel<<<NB, NCELL>>>();
    padfill_kernel<<<(NB * NPTS + 255) / 256, 256>>>();
    scatter_kernel<<<(NB * NPTS + 255) / 256, 256>>>();
    bounds_kernel<<<(NB * NCHK + 255) / 256, 256>>>();
    fraw_kernel<<<(NB * NPTS * CRAW + 255) / 256, 256>>>(points, W_raw, b_raw);
    fc3_kernel<<<(NB * MC3 * CC3 + 255) / 256, 256>>>(conv3, W_c3, b_c3);
    fps_kernel<<<NB, 512, fps_smem>>>();
    bev_kernel<<<dim3(NKP, NB), CBEV>>>(spatial);
    agg_raw_kernel<<<dim3(NKP / 8, NB), 256>>>(0.8f * 0.8f);
    agg_c3_kernel<<<dim3(NKP / 8, NB), 256>>>(1.6f * 1.6f);
    fuse_kernel<<<(NB * NKP) / ROWS_PB, COUT>>>(W_fuse, bn_g, bn_b, bn_m, bn_v, out);
    kpout_kernel<<<(NB * NKP * 3 + 255) / 256, 256>>>(out);
}